// round 3
// baseline (speedup 1.0000x reference)
#include <cuda_runtime.h>
#include <math.h>

// ============================================================================
// Famnet pipeline, fp32. Round 3: 128x128 SGEMM-style implicit-GEMM convs,
// chunked sim conv, fused conv4+conv5+max tail.
// ============================================================================

struct Geom {
    int top[2][2][3], left[2][2][3], bot[2][2][3], right[2][2][3];
    int PH[2][2], PW[2][2];
    int PHs[2][2][3], PWs[2][2][3];
};

static constexpr int SLOT = 4400000;

__device__ Geom  g_geom;
__device__ float g_x1[2 * 64 * 192 * 192];
__device__ float g_x2[2 * 256 * 96 * 96];
__device__ float g_f3[2 * 512 * 48 * 48];
__device__ float g_f4[2 * 1024 * 24 * 24];
__device__ float g_patches[4][SLOT];
__device__ float g_pf[12][SLOT];
__device__ float g_simraw[12][3 * 48 * 48];
__device__ float g_xr[6 * 6 * 48 * 48];
__device__ float g_r1[6 * 196 * 48 * 48];
__device__ float g_u1[6 * 196 * 96 * 96];
__device__ float g_r2[6 * 128 * 96 * 96];
__device__ float g_u2[6 * 128 * 192 * 192];
__device__ float g_r3[6 * 64 * 192 * 192];
__device__ float g_u3[6 * 64 * 384 * 384];

// ---------------- helpers ---------------------------------------------------
__device__ __forceinline__ float bilin_hp(const float* __restrict__ src, int sh, int sw,
                                          int stride, int oh, int ow, int i, int j) {
    float py = (i + 0.5f) * (float)sh / (float)oh - 0.5f;
    py = fminf(fmaxf(py, 0.f), (float)(sh - 1));
    int   y0 = (int)py; float ty = py - (float)y0; int y1 = min(y0 + 1, sh - 1);
    float px = (j + 0.5f) * (float)sw / (float)ow - 0.5f;
    px = fminf(fmaxf(px, 0.f), (float)(sw - 1));
    int   x0 = (int)px; float tx = px - (float)x0; int x1 = min(x0 + 1, sw - 1);
    float v00 = src[y0 * stride + x0], v01 = src[y0 * stride + x1];
    float v10 = src[y1 * stride + x0], v11 = src[y1 * stride + x1];
    return (1.f - ty) * ((1.f - tx) * v00 + tx * v01) + ty * ((1.f - tx) * v10 + tx * v11);
}

// ---------------- geometry (device-side) ------------------------------------
__global__ void setup_geom(const float* __restrict__ tlbrs) {
    if (threadIdx.x != 0 || blockIdx.x != 0) return;
    const double SC[3] = {1.0, 0.9, 1.1};
    for (int b = 0; b < 2; b++) {
        for (int f = 0; f < 2; f++) {
            const int FH = (f == 0) ? 48 : 24;
            const int FW = FH;
            const float scaling = 384.0f / (float)FH;
            int maxh = 0, maxw = 0;
            for (int p = 0; p < 3; p++) {
                const float* q = tlbrs + (b * 3 + p) * 4;
                float st = q[0] / scaling, sl = q[1] / scaling;
                float sb = q[2] / scaling, sr = q[3] / scaling;
                int top  = max(0, (int)floorf(st));
                int left = max(0, (int)floorf(sl));
                float bf = ceilf(sb) + 1.0f; if (bf > (float)FH) bf = (float)FH;
                float rf = ceilf(sr) + 1.0f; if (rf > (float)FW) rf = (float)FW;
                int bot = (int)bf, right = (int)rf;
                g_geom.top[b][f][p] = top;  g_geom.left[b][f][p] = left;
                g_geom.bot[b][f][p] = bot;  g_geom.right[b][f][p] = right;
                maxh = max(maxh, bot - top);
                maxw = max(maxw, right - left);
            }
            g_geom.PH[b][f] = maxh; g_geom.PW[b][f] = maxw;
            for (int s = 0; s < 3; s++) {
                int ph = (int)ceil((double)maxh * SC[s]); if (ph < 1) ph = maxh;
                int pw = (int)ceil((double)maxw * SC[s]); if (pw < 1) pw = maxw;
                g_geom.PHs[b][f][s] = ph; g_geom.PWs[b][f][s] = pw;
            }
        }
    }
}

// ---------------- implicit-GEMM conv, BK=8, 256 threads ---------------------
// BM x BN block tile; TM x TN thread tile (TM,TN in {4,8}); split-tile regs.
template <int K, int S, int BM, int BN, int TM, int TN>
__global__ __launch_bounds__(256, 2)
void convgemm(const float* __restrict__ in, const float* __restrict__ wgt,
              const float* __restrict__ bias, float* __restrict__ out,
              int Cin, int Hin, int Win, int Cout, int Hout, int Wout, int pad) {
    constexpr int KK = K * K;
    __shared__ float As[8][BM + 4];
    __shared__ float Bs[8][BN + 4];

    const int tid  = threadIdx.x;
    const int CKK  = Cin * KK;
    const int Npix = Hout * Wout;
    const int n    = blockIdx.z;
    const int co0  = blockIdx.y * BM;
    const int px0  = blockIdx.x * BN;

    const int tx = tid & 15;
    const int ty = tid >> 4;

    // ---- B (im2col) mapping: fixed pixel column per thread ----
    constexpr int KS    = 256 / BN;  // k-rows per pass
    constexpr int BPASS = 8 / KS;
    const int bn = tid % BN;
    const int bk = tid / BN;
    const int pixel = px0 + bn;
    const bool pv = pixel < Npix;
    const int py  = pv ? (pixel / Wout) : 0;
    const int pxx = pixel - py * Wout;
    const int iy0 = py * S - pad;
    const int ix0 = pxx * S - pad;
    const float* inN = in + (long)n * Cin * Hin * Win;
    const int HinWin = Hin * Win;

    // ---- A (weights) mapping ----
    constexpr int APASS = BM / 32;
    const int ak = tid & 7;
    const int am = tid >> 3;

    float acc[TM][TN] = {};

    for (int k0 = 0; k0 < CKK; k0 += 8) {
#pragma unroll
        for (int i = 0; i < APASS; i++) {
            int m  = am + i * 32;
            int kk = k0 + ak;
            float v = 0.f;
            if (co0 + m < Cout && kk < CKK)
                v = __ldg(wgt + (long)(co0 + m) * CKK + kk);
            As[ak][m] = v;
        }
#pragma unroll
        for (int i = 0; i < BPASS; i++) {
            int kb = bk + i * KS;
            int kk = k0 + kb;
            float v = 0.f;
            if (pv && kk < CKK) {
                int ci = kk / KK;
                int r  = kk - ci * KK;
                int ky = r / K;
                int kx = r - ky * K;
                int iy = iy0 + ky, ix = ix0 + kx;
                if ((unsigned)iy < (unsigned)Hin && (unsigned)ix < (unsigned)Win)
                    v = __ldg(inN + ci * HinWin + iy * Win + ix);
            }
            Bs[kb][bn] = v;
        }
        __syncthreads();
#pragma unroll
        for (int k = 0; k < 8; k++) {
            float a[TM], b[TN];
            *(float4*)&a[0] = *(const float4*)&As[k][ty * 4];
            if (TM == 8) *(float4*)&a[4] = *(const float4*)&As[k][64 + ty * 4];
            *(float4*)&b[0] = *(const float4*)&Bs[k][tx * 4];
            if (TN == 8) *(float4*)&b[4] = *(const float4*)&Bs[k][64 + tx * 4];
#pragma unroll
            for (int u = 0; u < TM; u++)
#pragma unroll
                for (int j = 0; j < TN; j++)
                    acc[u][j] = fmaf(a[u], b[j], acc[u][j]);
        }
        __syncthreads();
    }

    // ---- epilogue: bias + relu + vector store ----
    float* outN = out + (long)n * Cout * Npix;
#pragma unroll
    for (int u = 0; u < TM; u++) {
        const int row = (TM == 8) ? ((u < 4) ? (ty * 4 + u) : (64 + ty * 4 + u - 4))
                                  : (ty * 4 + u);
        const int co = co0 + row;
        if (co >= Cout) continue;
        const float bv = bias ? __ldg(bias + co) : 0.f;
#pragma unroll
        for (int jg = 0; jg < TN / 4; jg++) {
            const int colb = (jg == 0) ? (tx * 4) : (64 + tx * 4);
            const int pp = px0 + colb;
            if (pp < Npix) {
                float4 o;
                o.x = fmaxf(acc[u][jg * 4 + 0] + bv, 0.f);
                o.y = fmaxf(acc[u][jg * 4 + 1] + bv, 0.f);
                o.z = fmaxf(acc[u][jg * 4 + 2] + bv, 0.f);
                o.w = fmaxf(acc[u][jg * 4 + 3] + bv, 0.f);
                *(float4*)(outN + (long)co * Npix + pp) = o;
            }
        }
    }
}

// ---------------- patch extraction ------------------------------------------
__global__ void patch_extract() {
    const int cz = blockIdx.z;           // b*2 + f
    const int b = cz >> 1, f = cz & 1;
    const int FH = (f == 0) ? 48 : 24, FW = FH;
    const int FC = (f == 0) ? 512 : 1024;
    const int PH = g_geom.PH[b][f], PW = g_geom.PW[b][f];
    int total = 3 * FC * PH * PW;
    if (total > SLOT) total = SLOT;
    const float* fm = ((f == 0) ? (const float*)g_f3 : (const float*)g_f4) + (long)b * FC * FH * FW;
    float* dst = g_patches[cz];
    for (int idx = blockIdx.x * blockDim.x + threadIdx.x; idx < total;
         idx += gridDim.x * blockDim.x) {
        int j = idx % PW;
        int t = idx / PW;
        int i = t % PH; t /= PH;
        int c = t % FC;
        int p = t / FC;
        const int top = g_geom.top[b][f][p], left = g_geom.left[b][f][p];
        const int hp  = g_geom.bot[b][f][p] - top;
        const int wp  = g_geom.right[b][f][p] - left;
        const float* src = fm + (long)c * FH * FW + top * FW + left;
        dst[idx] = bilin_hp(src, hp, wp, FW, PH, PW, i, j);
    }
}

// ---------------- per-scale patch resize ------------------------------------
__global__ void pf_resize() {
    const int cz = blockIdx.z;
    const int s = cz % 3, f = (cz / 3) & 1, b = cz / 6;
    const int FC = (f == 0) ? 512 : 1024;
    const int PH = g_geom.PH[b][f], PW = g_geom.PW[b][f];
    const int PHs = g_geom.PHs[b][f][s], PWs = g_geom.PWs[b][f][s];
    int total = 3 * FC * PHs * PWs;
    if (total > SLOT) total = SLOT;
    const float* src = g_patches[b * 2 + f];
    float* dst = g_pf[cz];
    for (int idx = blockIdx.x * blockDim.x + threadIdx.x; idx < total;
         idx += gridDim.x * blockDim.x) {
        int j = idx % PWs;
        int t = idx / PWs;
        int i = t % PHs; t /= PHs;
        int c = t % FC;
        int p = t / FC;
        const float* sp = src + ((long)p * FC + c) * PH * PW;
        dst[idx] = bilin_hp(sp, PH, PW, PW, PHs, PWs, i, j);
    }
}

// ---------------- similarity conv v3: 4-channel chunks + clipped ranges -----
__global__ __launch_bounds__(128) void sim_conv3() {
    constexpr int CH = 4;
    const int cz = blockIdx.z;           // (b*2+f)*3 + s
    const int s = cz % 3, f = (cz / 3) & 1, b = cz / 6;
    const int FH = f ? 24 : 48, FW = FH;
    const int FC = f ? 1024 : 512;
    const int npx = FH * FW;
    if (blockIdx.y * 128 >= npx) return;   // uniform block exit

    const int PHs = g_geom.PHs[b][f][s], PWs = g_geom.PWs[b][f][s];
    int W = PHs * PWs;
    if (W > 324) W = 324;                  // defensive (true max is 256)
    const int pt = PHs >> 1, pl = PWs >> 1;

    int pix = blockIdx.y * 128 + threadIdx.x;
    const bool act = pix < npx;
    if (!act) pix = npx - 1;
    const int y = pix / FW, x = pix - (pix / FW) * FW;

    const int ky0 = max(0, pt - y), ky1 = min(PHs, FH + pt - y);
    const int kx0 = max(0, pl - x), kx1 = min(PWs, FW + pl - x);

    const float* fm  = (f ? (const float*)g_f4 : (const float*)g_f3) + (long)b * FC * FH * FW;
    const float* pfp = g_pf[cz];

    __shared__ float spf[CH][3][324];
    float a0 = 0.f, a1 = 0.f, a2 = 0.f;

    for (int c0 = 0; c0 < FC; c0 += CH) {
        __syncthreads();
        for (int t = threadIdx.x; t < 3 * CH * W; t += 128) {
            int p  = t / (CH * W);
            int r  = t - p * (CH * W);
            int cc = r / W;
            int w  = r - cc * W;
            spf[cc][p][w] = __ldg(pfp + ((long)p * FC + c0 + cc) * W + w);
        }
        __syncthreads();
#pragma unroll
        for (int cc = 0; cc < CH; cc++) {
            const float* fmc = fm + (long)(c0 + cc) * npx;
            for (int ky = ky0; ky < ky1; ky++) {
                const float* row = fmc + (y - pt + ky) * FW + (x - pl);
                const int wb = ky * PWs;
                for (int kx = kx0; kx < kx1; kx++) {
                    float fv = __ldg(row + kx);
                    a0 = fmaf(fv, spf[cc][0][wb + kx], a0);
                    a1 = fmaf(fv, spf[cc][1][wb + kx], a1);
                    a2 = fmaf(fv, spf[cc][2][wb + kx], a2);
                }
            }
        }
    }
    if (act) {
        g_simraw[cz][0 * npx + pix] = a0;
        g_simraw[cz][1 * npx + pix] = a1;
        g_simraw[cz][2 * npx + pix] = a2;
    }
}

// ---------------- assemble regressor input (6,6,48,48) ----------------------
__global__ void build_xr() {
    const int idx = blockIdx.x * blockDim.x + threadIdx.x;
    if (idx >= 6 * 6 * 48 * 48) return;
    const int x = idx % 48;
    const int y = (idx / 48) % 48;
    const int ch = (idx / 2304) % 6;
    const int n = idx / (2304 * 6);
    const int b = n / 3, p = n % 3;
    const int f = (ch < 3) ? 0 : 1;
    const int s = ch % 3;
    const int cz = (b * 2 + f) * 3 + s;
    float v;
    if (f == 0) {
        v = g_simraw[cz][p * 2304 + y * 48 + x];
    } else {
        const float* src = g_simraw[cz] + p * 576;
        v = bilin_hp(src, 24, 24, 24, 48, 48, y, x);
    }
    g_xr[idx] = v;
}

// ---------------- align_corners 2x upsample ---------------------------------
__global__ void upsample2x_kernel(const float* __restrict__ in, float* __restrict__ out,
                                  int NC, int H, int W) {
    const int Ho = 2 * H, Wo = 2 * W;
    const long total = (long)NC * Ho * Wo;
    const float sy = (float)(H - 1) / (float)(Ho - 1);
    const float sx = (float)(W - 1) / (float)(Wo - 1);
    for (long idx = (long)blockIdx.x * blockDim.x + threadIdx.x; idx < total;
         idx += (long)gridDim.x * blockDim.x) {
        int x = (int)(idx % Wo);
        long t = idx / Wo;
        int y = (int)(t % Ho);
        int c = (int)(t / Ho);
        float py = y * sy; int y0 = (int)py; float ty = py - y0; int y1 = min(y0 + 1, H - 1);
        float px = x * sx; int x0 = (int)px; float tx = px - x0; int x1 = min(x0 + 1, W - 1);
        const float* p = in + (long)c * H * W;
        out[idx] = (1.f - ty) * ((1.f - tx) * p[y0 * W + x0] + tx * p[y0 * W + x1]) +
                   ty * ((1.f - tx) * p[y1 * W + x0] + tx * p[y1 * W + x1]);
    }
}

// ---------------- fused conv4(1x1,64->32)+relu + conv5(1x1)+relu + max ------
__global__ __launch_bounds__(256)
void finalfuse(const float* __restrict__ u3,
               const float* __restrict__ rw4, const float* __restrict__ rb4,
               const float* __restrict__ rw5, const float* __restrict__ rb5,
               float* __restrict__ out) {
    __shared__ float sW[2048];   // rw4 [32][64]
    __shared__ float sb4[32], sw5[32];
    __shared__ float sb5v;
    for (int t = threadIdx.x; t < 2048; t += 256) sW[t] = rw4[t];
    if (threadIdx.x < 32) { sb4[threadIdx.x] = rb4[threadIdx.x]; sw5[threadIdx.x] = rw5[threadIdx.x]; }
    if (threadIdx.x == 0) sb5v = rb5[0];
    __syncthreads();

    const int idx = blockIdx.x * 256 + threadIdx.x;
    if (idx >= 2 * 147456) return;
    const int b = idx / 147456;
    const int pos = idx - b * 147456;

    float m = -1e30f;
    for (int p = 0; p < 3; p++) {
        const float* base = u3 + ((long)(b * 3 + p) * 64) * 147456 + pos;
        float acc[32];
#pragma unroll
        for (int o = 0; o < 32; o++) acc[o] = sb4[o];
#pragma unroll
        for (int c0 = 0; c0 < 64; c0 += 16) {
            float v[16];
#pragma unroll
            for (int i = 0; i < 16; i++) v[i] = __ldg(base + (long)(c0 + i) * 147456);
#pragma unroll
            for (int o = 0; o < 32; o++) {
                const float4 w0 = *(const float4*)&sW[o * 64 + c0];
                const float4 w1 = *(const float4*)&sW[o * 64 + c0 + 4];
                const float4 w2 = *(const float4*)&sW[o * 64 + c0 + 8];
                const float4 w3 = *(const float4*)&sW[o * 64 + c0 + 12];
                float a = acc[o];
                a = fmaf(v[0], w0.x, a);  a = fmaf(v[1], w0.y, a);
                a = fmaf(v[2], w0.z, a);  a = fmaf(v[3], w0.w, a);
                a = fmaf(v[4], w1.x, a);  a = fmaf(v[5], w1.y, a);
                a = fmaf(v[6], w1.z, a);  a = fmaf(v[7], w1.w, a);
                a = fmaf(v[8], w2.x, a);  a = fmaf(v[9], w2.y, a);
                a = fmaf(v[10], w2.z, a); a = fmaf(v[11], w2.w, a);
                a = fmaf(v[12], w3.x, a); a = fmaf(v[13], w3.y, a);
                a = fmaf(v[14], w3.z, a); a = fmaf(v[15], w3.w, a);
                acc[o] = a;
            }
        }
        float a5 = sb5v;
#pragma unroll
        for (int o = 0; o < 32; o++) a5 = fmaf(sw5[o], fmaxf(acc[o], 0.f), a5);
        m = fmaxf(m, fmaxf(a5, 0.f));
    }
    out[idx] = m;
}

// ---------------- host launcher ---------------------------------------------
template <int K, int S, int BM, int BN, int TM, int TN>
static void run_conv(const float* in, const float* w, const float* bias, float* out,
                     int N, int Cin, int Hin, int Win, int Cout, int pad) {
    const int Hout = (Hin + 2 * pad - K) / S + 1;
    const int Wout = (Win + 2 * pad - K) / S + 1;
    const int Npix = Hout * Wout;
    dim3 grid((Npix + BN - 1) / BN, (Cout + BM - 1) / BM, N);
    convgemm<K, S, BM, BN, TM, TN><<<grid, 256>>>(in, w, bias, out,
                                                  Cin, Hin, Win, Cout, Hout, Wout, pad);
}

extern "C" void kernel_launch(void* const* d_in, const int* in_sizes, int n_in,
                              void* d_out, int out_size) {
    const float* images = (const float*)d_in[0];
    const float* tlbrs  = (const float*)d_in[1];
    const float* fw1 = (const float*)d_in[2];
    const float* fw2 = (const float*)d_in[3];
    const float* fw3 = (const float*)d_in[4];
    const float* fw4 = (const float*)d_in[5];
    const float* rw1 = (const float*)d_in[6];
    const float* rb1 = (const float*)d_in[7];
    const float* rw2 = (const float*)d_in[8];
    const float* rb2 = (const float*)d_in[9];
    const float* rw3 = (const float*)d_in[10];
    const float* rb3 = (const float*)d_in[11];
    const float* rw4 = (const float*)d_in[12];
    const float* rb4 = (const float*)d_in[13];
    const float* rw5 = (const float*)d_in[14];
    const float* rb5 = (const float*)d_in[15];

    float *x1, *x2, *f3, *f4, *xr, *r1, *u1, *r2, *u2, *r3, *u3;
    cudaGetSymbolAddress((void**)&x1, g_x1);
    cudaGetSymbolAddress((void**)&x2, g_x2);
    cudaGetSymbolAddress((void**)&f3, g_f3);
    cudaGetSymbolAddress((void**)&f4, g_f4);
    cudaGetSymbolAddress((void**)&xr, g_xr);
    cudaGetSymbolAddress((void**)&r1, g_r1);
    cudaGetSymbolAddress((void**)&u1, g_u1);
    cudaGetSymbolAddress((void**)&r2, g_r2);
    cudaGetSymbolAddress((void**)&u2, g_u2);
    cudaGetSymbolAddress((void**)&r3, g_r3);
    cudaGetSymbolAddress((void**)&u3, g_u3);

    setup_geom<<<1, 1>>>(tlbrs);

    // backbone
    run_conv<7, 2,  64, 128, 4, 8>(images, fw1, nullptr, x1, 2,   3, 384, 384,   64, 3);
    run_conv<3, 2, 128, 128, 8, 8>(x1,     fw2, nullptr, x2, 2,  64, 192, 192,  256, 1);
    run_conv<3, 2, 128, 128, 8, 8>(x2,     fw3, nullptr, f3, 2, 256,  96,  96,  512, 1);
    run_conv<3, 2, 128,  64, 8, 4>(f3,     fw4, nullptr, f4, 2, 512,  48,  48, 1024, 1);

    // exemplar patches + similarity maps
    patch_extract<<<dim3(512, 1, 4), 256>>>();
    pf_resize<<<dim3(512, 1, 12), 256>>>();
    sim_conv3<<<dim3(1, 18, 12), 128>>>();
    build_xr<<<(6 * 6 * 48 * 48 + 255) / 256, 256>>>();

    // count regressor
    run_conv<7, 1, 128, 128, 8, 8>(xr, rw1, rb1, r1, 6,   6,  48,  48, 196, 3);
    upsample2x_kernel<<<(6 * 196 * 96 * 96 + 255) / 256, 256>>>(r1, u1, 6 * 196, 48, 48);
    run_conv<5, 1, 128, 128, 8, 8>(u1, rw2, rb2, r2, 6, 196,  96,  96, 128, 2);
    upsample2x_kernel<<<(6 * 128 * 192 * 192 + 255) / 256, 256>>>(r2, u2, 6 * 128, 96, 96);
    run_conv<3, 1,  64, 128, 4, 8>(u2, rw3, rb3, r3, 6, 128, 192, 192,  64, 1);
    upsample2x_kernel<<<(6 * 64 * 384 * 384 + 255) / 256, 256>>>(r3, u3, 6 * 64, 192, 192);

    // conv4 + conv5 + max over P, straight into d_out
    finalfuse<<<(2 * 147456 + 255) / 256, 256>>>(u3, rw4, rb4, rw5, rb5, (float*)d_out);
}

// round 5
// speedup vs baseline: 1.0810x; 1.0810x over previous
#include <cuda_runtime.h>
#include <math.h>

// ============================================================================
// Famnet pipeline, fp32. Round 5 (= round 4 rerun after infra failure):
// double-buffered 64x64x16 implicit-GEMM convs, chunked sim conv,
// fused conv4+conv5+max tail.
// ============================================================================

struct Geom {
    int top[2][2][3], left[2][2][3], bot[2][2][3], right[2][2][3];
    int PH[2][2], PW[2][2];
    int PHs[2][2][3], PWs[2][2][3];
};

static constexpr int SLOT = 4400000;

__device__ Geom  g_geom;
__device__ float g_x1[2 * 64 * 192 * 192];
__device__ float g_x2[2 * 256 * 96 * 96];
__device__ float g_f3[2 * 512 * 48 * 48];
__device__ float g_f4[2 * 1024 * 24 * 24];
__device__ float g_patches[4][SLOT];
__device__ float g_pf[12][SLOT];
__device__ float g_simraw[12][3 * 48 * 48];
__device__ float g_xr[6 * 6 * 48 * 48];
__device__ float g_r1[6 * 196 * 48 * 48];
__device__ float g_u1[6 * 196 * 96 * 96];
__device__ float g_r2[6 * 128 * 96 * 96];
__device__ float g_u2[6 * 128 * 192 * 192];
__device__ float g_r3[6 * 64 * 192 * 192];
__device__ float g_u3[6 * 64 * 384 * 384];

// ---------------- helpers ---------------------------------------------------
__device__ __forceinline__ float bilin_hp(const float* __restrict__ src, int sh, int sw,
                                          int stride, int oh, int ow, int i, int j) {
    float py = (i + 0.5f) * (float)sh / (float)oh - 0.5f;
    py = fminf(fmaxf(py, 0.f), (float)(sh - 1));
    int   y0 = (int)py; float ty = py - (float)y0; int y1 = min(y0 + 1, sh - 1);
    float px = (j + 0.5f) * (float)sw / (float)ow - 0.5f;
    px = fminf(fmaxf(px, 0.f), (float)(sw - 1));
    int   x0 = (int)px; float tx = px - (float)x0; int x1 = min(x0 + 1, sw - 1);
    float v00 = src[y0 * stride + x0], v01 = src[y0 * stride + x1];
    float v10 = src[y1 * stride + x0], v11 = src[y1 * stride + x1];
    return (1.f - ty) * ((1.f - tx) * v00 + tx * v01) + ty * ((1.f - tx) * v10 + tx * v11);
}

// ---------------- geometry (device-side) ------------------------------------
__global__ void setup_geom(const float* __restrict__ tlbrs) {
    if (threadIdx.x != 0 || blockIdx.x != 0) return;
    const double SC[3] = {1.0, 0.9, 1.1};
    for (int b = 0; b < 2; b++) {
        for (int f = 0; f < 2; f++) {
            const int FH = (f == 0) ? 48 : 24;
            const int FW = FH;
            const float scaling = 384.0f / (float)FH;
            int maxh = 0, maxw = 0;
            for (int p = 0; p < 3; p++) {
                const float* q = tlbrs + (b * 3 + p) * 4;
                float st = q[0] / scaling, sl = q[1] / scaling;
                float sb = q[2] / scaling, sr = q[3] / scaling;
                int top  = max(0, (int)floorf(st));
                int left = max(0, (int)floorf(sl));
                float bf = ceilf(sb) + 1.0f; if (bf > (float)FH) bf = (float)FH;
                float rf = ceilf(sr) + 1.0f; if (rf > (float)FW) rf = (float)FW;
                int bot = (int)bf, right = (int)rf;
                g_geom.top[b][f][p] = top;  g_geom.left[b][f][p] = left;
                g_geom.bot[b][f][p] = bot;  g_geom.right[b][f][p] = right;
                maxh = max(maxh, bot - top);
                maxw = max(maxw, right - left);
            }
            g_geom.PH[b][f] = maxh; g_geom.PW[b][f] = maxw;
            for (int s = 0; s < 3; s++) {
                int ph = (int)ceil((double)maxh * SC[s]); if (ph < 1) ph = maxh;
                int pw = (int)ceil((double)maxw * SC[s]); if (pw < 1) pw = maxw;
                g_geom.PHs[b][f][s] = ph; g_geom.PWs[b][f][s] = pw;
            }
        }
    }
}

// ---------------- double-buffered implicit-GEMM conv ------------------------
// BM=BN=64, BK=16, 256 threads, 4x4 thread tile, register prefetch.
template <int K, int S>
__global__ __launch_bounds__(256, 3)
void convgemm(const float* __restrict__ in, const float* __restrict__ wgt,
              const float* __restrict__ bias, float* __restrict__ out,
              int Cin, int Hin, int Win, int Cout, int Hout, int Wout, int pad) {
    constexpr int KK = K * K;
    __shared__ float As[2][16][68];
    __shared__ float Bs[2][16][68];

    const int tid  = threadIdx.x;
    const int CKK  = Cin * KK;
    const int Npix = Hout * Wout;
    const int n    = blockIdx.z;
    const int co0  = blockIdx.y * 64;
    const int px0  = blockIdx.x * 64;

    const int ty = tid >> 4;      // 0..15
    const int tx = tid & 15;      // 0..15

    // B (im2col) mapping: fixed pixel column per thread, 4 k-rows
    const int bn = tid & 63;
    const int bk = tid >> 6;      // 0..3, rows bk+4i
    const int pixel = px0 + bn;
    const bool pv = pixel < Npix;
    const int py  = pv ? (pixel / Wout) : 0;
    const int pxx = pixel - py * Wout;
    const int iy0 = py * S - pad;
    const int ix0 = pxx * S - pad;
    const float* inN = in + (long)n * Cin * Hin * Win;
    const int HinWin = Hin * Win;

    // A (weights) mapping: k-col ak, 4 m-rows am+16i
    const int ak = tid & 15;
    const int am = tid >> 4;

    auto loadA = [&](int k0, int i) -> float {
        int kk = k0 + ak;
        int m  = am + i * 16;
        float v = 0.f;
        if (kk < CKK && co0 + m < Cout)
            v = __ldg(wgt + (long)(co0 + m) * CKK + kk);
        return v;
    };
    auto loadB = [&](int k0, int i) -> float {
        int kb = bk + i * 4;
        int kk = k0 + kb;
        float v = 0.f;
        if (pv && kk < CKK) {
            int ci = kk / KK;
            int r  = kk - ci * KK;
            int ky = r / K;
            int kx = r - ky * K;
            int iy = iy0 + ky, ix = ix0 + kx;
            if ((unsigned)iy < (unsigned)Hin && (unsigned)ix < (unsigned)Win)
                v = __ldg(inN + ci * HinWin + iy * Win + ix);
        }
        return v;
    };

    float acc[4][4] = {};
    const int nk = (CKK + 15) >> 4;

    // preload tile 0
#pragma unroll
    for (int i = 0; i < 4; i++) As[0][ak][am + i * 16] = loadA(0, i);
#pragma unroll
    for (int i = 0; i < 4; i++) Bs[0][bk + i * 4][bn] = loadB(0, i);
    __syncthreads();

    for (int t = 0; t < nk; t++) {
        const int cur = t & 1, nxt = cur ^ 1;
        const bool more = (t + 1 < nk);
        float aP[4], bP[4];
        if (more) {
            const int k0 = (t + 1) << 4;
#pragma unroll
            for (int i = 0; i < 4; i++) aP[i] = loadA(k0, i);
#pragma unroll
            for (int i = 0; i < 4; i++) bP[i] = loadB(k0, i);
        }
#pragma unroll
        for (int k = 0; k < 16; k++) {
            float4 a = *(const float4*)&As[cur][k][ty * 4];
            float4 b = *(const float4*)&Bs[cur][k][tx * 4];
            float av[4] = {a.x, a.y, a.z, a.w};
            float bv[4] = {b.x, b.y, b.z, b.w};
#pragma unroll
            for (int u = 0; u < 4; u++)
#pragma unroll
                for (int j = 0; j < 4; j++)
                    acc[u][j] = fmaf(av[u], bv[j], acc[u][j]);
        }
        if (more) {
#pragma unroll
            for (int i = 0; i < 4; i++) As[nxt][ak][am + i * 16] = aP[i];
#pragma unroll
            for (int i = 0; i < 4; i++) Bs[nxt][bk + i * 4][bn] = bP[i];
        }
        __syncthreads();
    }

    // epilogue: bias + relu + vector store
    float* outN = out + (long)n * Cout * Npix;
#pragma unroll
    for (int u = 0; u < 4; u++) {
        const int co = co0 + ty * 4 + u;
        if (co >= Cout) continue;
        const float bv = bias ? __ldg(bias + co) : 0.f;
        const int pp = px0 + tx * 4;
        if (pp + 3 < Npix) {
            float4 o;
            o.x = fmaxf(acc[u][0] + bv, 0.f);
            o.y = fmaxf(acc[u][1] + bv, 0.f);
            o.z = fmaxf(acc[u][2] + bv, 0.f);
            o.w = fmaxf(acc[u][3] + bv, 0.f);
            *(float4*)(outN + (long)co * Npix + pp) = o;
        } else {
#pragma unroll
            for (int j = 0; j < 4; j++)
                if (pp + j < Npix)
                    outN[(long)co * Npix + pp + j] = fmaxf(acc[u][j] + bv, 0.f);
        }
    }
}

// ---------------- patch extraction ------------------------------------------
__global__ void patch_extract() {
    const int cz = blockIdx.z;           // b*2 + f
    const int b = cz >> 1, f = cz & 1;
    const int FH = (f == 0) ? 48 : 24, FW = FH;
    const int FC = (f == 0) ? 512 : 1024;
    const int PH = g_geom.PH[b][f], PW = g_geom.PW[b][f];
    int total = 3 * FC * PH * PW;
    if (total > SLOT) total = SLOT;
    const float* fm = ((f == 0) ? (const float*)g_f3 : (const float*)g_f4) + (long)b * FC * FH * FW;
    float* dst = g_patches[cz];
    for (int idx = blockIdx.x * blockDim.x + threadIdx.x; idx < total;
         idx += gridDim.x * blockDim.x) {
        int j = idx % PW;
        int t = idx / PW;
        int i = t % PH; t /= PH;
        int c = t % FC;
        int p = t / FC;
        const int top = g_geom.top[b][f][p], left = g_geom.left[b][f][p];
        const int hp  = g_geom.bot[b][f][p] - top;
        const int wp  = g_geom.right[b][f][p] - left;
        const float* src = fm + (long)c * FH * FW + top * FW + left;
        dst[idx] = bilin_hp(src, hp, wp, FW, PH, PW, i, j);
    }
}

// ---------------- per-scale patch resize ------------------------------------
__global__ void pf_resize() {
    const int cz = blockIdx.z;
    const int s = cz % 3, f = (cz / 3) & 1, b = cz / 6;
    const int FC = (f == 0) ? 512 : 1024;
    const int PH = g_geom.PH[b][f], PW = g_geom.PW[b][f];
    const int PHs = g_geom.PHs[b][f][s], PWs = g_geom.PWs[b][f][s];
    int total = 3 * FC * PHs * PWs;
    if (total > SLOT) total = SLOT;
    const float* src = g_patches[b * 2 + f];
    float* dst = g_pf[cz];
    for (int idx = blockIdx.x * blockDim.x + threadIdx.x; idx < total;
         idx += gridDim.x * blockDim.x) {
        int j = idx % PWs;
        int t = idx / PWs;
        int i = t % PHs; t /= PHs;
        int c = t % FC;
        int p = t / FC;
        const float* sp = src + ((long)p * FC + c) * PH * PW;
        dst[idx] = bilin_hp(sp, PH, PW, PW, PHs, PWs, i, j);
    }
}

// ---------------- similarity conv: 4-channel chunks + clipped ranges --------
__global__ __launch_bounds__(128) void sim_conv3() {
    constexpr int CH = 4;
    const int cz = blockIdx.z;           // (b*2+f)*3 + s
    const int s = cz % 3, f = (cz / 3) & 1, b = cz / 6;
    const int FH = f ? 24 : 48, FW = FH;
    const int FC = f ? 1024 : 512;
    const int npx = FH * FW;
    if (blockIdx.y * 128 >= npx) return;   // uniform block exit

    const int PHs = g_geom.PHs[b][f][s], PWs = g_geom.PWs[b][f][s];
    int W = PHs * PWs;
    if (W > 324) W = 324;                  // defensive
    const int pt = PHs >> 1, pl = PWs >> 1;

    int pix = blockIdx.y * 128 + threadIdx.x;
    const bool act = pix < npx;
    if (!act) pix = npx - 1;
    const int y = pix / FW, x = pix - (pix / FW) * FW;

    const int ky0 = max(0, pt - y), ky1 = min(PHs, FH + pt - y);
    const int kx0 = max(0, pl - x), kx1 = min(PWs, FW + pl - x);

    const float* fm  = (f ? (const float*)g_f4 : (const float*)g_f3) + (long)b * FC * FH * FW;
    const float* pfp = g_pf[cz];

    __shared__ float spf[CH][3][324];
    float a0 = 0.f, a1 = 0.f, a2 = 0.f;

    for (int c0 = 0; c0 < FC; c0 += CH) {
        __syncthreads();
        for (int t = threadIdx.x; t < 3 * CH * W; t += 128) {
            int p  = t / (CH * W);
            int r  = t - p * (CH * W);
            int cc = r / W;
            int w  = r - cc * W;
            spf[cc][p][w] = __ldg(pfp + ((long)p * FC + c0 + cc) * W + w);
        }
        __syncthreads();
#pragma unroll
        for (int cc = 0; cc < CH; cc++) {
            const float* fmc = fm + (long)(c0 + cc) * npx;
            for (int ky = ky0; ky < ky1; ky++) {
                const float* row = fmc + (y - pt + ky) * FW + (x - pl);
                const int wb = ky * PWs;
                for (int kx = kx0; kx < kx1; kx++) {
                    float fv = __ldg(row + kx);
                    a0 = fmaf(fv, spf[cc][0][wb + kx], a0);
                    a1 = fmaf(fv, spf[cc][1][wb + kx], a1);
                    a2 = fmaf(fv, spf[cc][2][wb + kx], a2);
                }
            }
        }
    }
    if (act) {
        g_simraw[cz][0 * npx + pix] = a0;
        g_simraw[cz][1 * npx + pix] = a1;
        g_simraw[cz][2 * npx + pix] = a2;
    }
}

// ---------------- assemble regressor input (6,6,48,48) ----------------------
__global__ void build_xr() {
    const int idx = blockIdx.x * blockDim.x + threadIdx.x;
    if (idx >= 6 * 6 * 48 * 48) return;
    const int x = idx % 48;
    const int y = (idx / 48) % 48;
    const int ch = (idx / 2304) % 6;
    const int n = idx / (2304 * 6);
    const int b = n / 3, p = n % 3;
    const int f = (ch < 3) ? 0 : 1;
    const int s = ch % 3;
    const int cz = (b * 2 + f) * 3 + s;
    float v;
    if (f == 0) {
        v = g_simraw[cz][p * 2304 + y * 48 + x];
    } else {
        const float* src = g_simraw[cz] + p * 576;
        v = bilin_hp(src, 24, 24, 24, 48, 48, y, x);
    }
    g_xr[idx] = v;
}

// ---------------- align_corners 2x upsample ---------------------------------
__global__ void upsample2x_kernel(const float* __restrict__ in, float* __restrict__ out,
                                  int NC, int H, int W) {
    const int Ho = 2 * H, Wo = 2 * W;
    const long total = (long)NC * Ho * Wo;
    const float sy = (float)(H - 1) / (float)(Ho - 1);
    const float sx = (float)(W - 1) / (float)(Wo - 1);
    for (long idx = (long)blockIdx.x * blockDim.x + threadIdx.x; idx < total;
         idx += (long)gridDim.x * blockDim.x) {
        int x = (int)(idx % Wo);
        long t = idx / Wo;
        int y = (int)(t % Ho);
        int c = (int)(t / Ho);
        float py = y * sy; int y0 = (int)py; float ty = py - y0; int y1 = min(y0 + 1, H - 1);
        float px = x * sx; int x0 = (int)px; float tx = px - x0; int x1 = min(x0 + 1, W - 1);
        const float* p = in + (long)c * H * W;
        out[idx] = (1.f - ty) * ((1.f - tx) * p[y0 * W + x0] + tx * p[y0 * W + x1]) +
                   ty * ((1.f - tx) * p[y1 * W + x0] + tx * p[y1 * W + x1]);
    }
}

// ---------------- fused conv4(1x1,64->32)+relu + conv5(1x1)+relu + max ------
__global__ __launch_bounds__(256)
void finalfuse(const float* __restrict__ u3,
               const float* __restrict__ rw4, const float* __restrict__ rb4,
               const float* __restrict__ rw5, const float* __restrict__ rb5,
               float* __restrict__ out) {
    __shared__ float sW[2048];   // rw4 [32][64]
    __shared__ float sb4[32], sw5[32];
    __shared__ float sb5v;
    for (int t = threadIdx.x; t < 2048; t += 256) sW[t] = rw4[t];
    if (threadIdx.x < 32) { sb4[threadIdx.x] = rb4[threadIdx.x]; sw5[threadIdx.x] = rw5[threadIdx.x]; }
    if (threadIdx.x == 0) sb5v = rb5[0];
    __syncthreads();

    const int idx = blockIdx.x * 256 + threadIdx.x;
    if (idx >= 2 * 147456) return;
    const int b = idx / 147456;
    const int pos = idx - b * 147456;

    float m = -1e30f;
    for (int p = 0; p < 3; p++) {
        const float* base = u3 + ((long)(b * 3 + p) * 64) * 147456 + pos;
        float acc[32];
#pragma unroll
        for (int o = 0; o < 32; o++) acc[o] = sb4[o];
#pragma unroll
        for (int c0 = 0; c0 < 64; c0 += 16) {
            float v[16];
#pragma unroll
            for (int i = 0; i < 16; i++) v[i] = __ldg(base + (long)(c0 + i) * 147456);
#pragma unroll
            for (int o = 0; o < 32; o++) {
                const float4 w0 = *(const float4*)&sW[o * 64 + c0];
                const float4 w1 = *(const float4*)&sW[o * 64 + c0 + 4];
                const float4 w2 = *(const float4*)&sW[o * 64 + c0 + 8];
                const float4 w3 = *(const float4*)&sW[o * 64 + c0 + 12];
                float a = acc[o];
                a = fmaf(v[0], w0.x, a);  a = fmaf(v[1], w0.y, a);
                a = fmaf(v[2], w0.z, a);  a = fmaf(v[3], w0.w, a);
                a = fmaf(v[4], w1.x, a);  a = fmaf(v[5], w1.y, a);
                a = fmaf(v[6], w1.z, a);  a = fmaf(v[7], w1.w, a);
                a = fmaf(v[8], w2.x, a);  a = fmaf(v[9], w2.y, a);
                a = fmaf(v[10], w2.z, a); a = fmaf(v[11], w2.w, a);
                a = fmaf(v[12], w3.x, a); a = fmaf(v[13], w3.y, a);
                a = fmaf(v[14], w3.z, a); a = fmaf(v[15], w3.w, a);
                acc[o] = a;
            }
        }
        float a5 = sb5v;
#pragma unroll
        for (int o = 0; o < 32; o++) a5 = fmaf(sw5[o], fmaxf(acc[o], 0.f), a5);
        m = fmaxf(m, fmaxf(a5, 0.f));
    }
    out[idx] = m;
}

// ---------------- host launcher ---------------------------------------------
template <int K, int S>
static void run_conv(const float* in, const float* w, const float* bias, float* out,
                     int N, int Cin, int Hin, int Win, int Cout, int pad) {
    const int Hout = (Hin + 2 * pad - K) / S + 1;
    const int Wout = (Win + 2 * pad - K) / S + 1;
    const int Npix = Hout * Wout;
    dim3 grid((Npix + 63) / 64, (Cout + 63) / 64, N);
    convgemm<K, S><<<grid, 256>>>(in, w, bias, out, Cin, Hin, Win, Cout, Hout, Wout, pad);
}

extern "C" void kernel_launch(void* const* d_in, const int* in_sizes, int n_in,
                              void* d_out, int out_size) {
    const float* images = (const float*)d_in[0];
    const float* tlbrs  = (const float*)d_in[1];
    const float* fw1 = (const float*)d_in[2];
    const float* fw2 = (const float*)d_in[3];
    const float* fw3 = (const float*)d_in[4];
    const float* fw4 = (const float*)d_in[5];
    const float* rw1 = (const float*)d_in[6];
    const float* rb1 = (const float*)d_in[7];
    const float* rw2 = (const float*)d_in[8];
    const float* rb2 = (const float*)d_in[9];
    const float* rw3 = (const float*)d_in[10];
    const float* rb3 = (const float*)d_in[11];
    const float* rw4 = (const float*)d_in[12];
    const float* rb4 = (const float*)d_in[13];
    const float* rw5 = (const float*)d_in[14];
    const float* rb5 = (const float*)d_in[15];

    float *x1, *x2, *f3, *f4, *xr, *r1, *u1, *r2, *u2, *r3, *u3;
    cudaGetSymbolAddress((void**)&x1, g_x1);
    cudaGetSymbolAddress((void**)&x2, g_x2);
    cudaGetSymbolAddress((void**)&f3, g_f3);
    cudaGetSymbolAddress((void**)&f4, g_f4);
    cudaGetSymbolAddress((void**)&xr, g_xr);
    cudaGetSymbolAddress((void**)&r1, g_r1);
    cudaGetSymbolAddress((void**)&u1, g_u1);
    cudaGetSymbolAddress((void**)&r2, g_r2);
    cudaGetSymbolAddress((void**)&u2, g_u2);
    cudaGetSymbolAddress((void**)&r3, g_r3);
    cudaGetSymbolAddress((void**)&u3, g_u3);

    setup_geom<<<1, 1>>>(tlbrs);

    // backbone
    run_conv<7, 2>(images, fw1, nullptr, x1, 2,   3, 384, 384,   64, 3);
    run_conv<3, 2>(x1,     fw2, nullptr, x2, 2,  64, 192, 192,  256, 1);
    run_conv<3, 2>(x2,     fw3, nullptr, f3, 2, 256,  96,  96,  512, 1);
    run_conv<3, 2>(f3,     fw4, nullptr, f4, 2, 512,  48,  48, 1024, 1);

    // exemplar patches + similarity maps
    patch_extract<<<dim3(512, 1, 4), 256>>>();
    pf_resize<<<dim3(512, 1, 12), 256>>>();
    sim_conv3<<<dim3(1, 18, 12), 128>>>();
    build_xr<<<(6 * 6 * 48 * 48 + 255) / 256, 256>>>();

    // count regressor
    run_conv<7, 1>(xr, rw1, rb1, r1, 6,   6,  48,  48, 196, 3);
    upsample2x_kernel<<<(6 * 196 * 96 * 96 + 255) / 256, 256>>>(r1, u1, 6 * 196, 48, 48);
    run_conv<5, 1>(u1, rw2, rb2, r2, 6, 196,  96,  96, 128, 2);
    upsample2x_kernel<<<(6 * 128 * 192 * 192 + 255) / 256, 256>>>(r2, u2, 6 * 128, 96, 96);
    run_conv<3, 1>(u2, rw3, rb3, r3, 6, 128, 192, 192,  64, 1);
    upsample2x_kernel<<<(6 * 64 * 384 * 384 + 255) / 256, 256>>>(r3, u3, 6 * 64, 192, 192);

    // conv4 + conv5 + max over P, straight into d_out
    finalfuse<<<(2 * 147456 + 255) / 256, 256>>>(u3, rw4, rb4, rw5, rb5, (float*)d_out);
}